// round 1
// baseline (speedup 1.0000x reference)
#include <cuda_runtime.h>
#include <math.h>

#define NB   16
#define NL   1024
#define ND   512
#define NDH  64
#define KTOP 13

// Scratch (no allocations allowed): 4 x 4MB fp32
__device__ float g_qp[NB * NDH * NL];   // q projection, [b][d][l]
__device__ float g_kp[NB * NDH * NL];   // k projection, [b][d][l]
__device__ float g_vp[NB * NDH * NL];   // v projection, [b][d][l]
__device__ float g_agg[NB * NDH * NL];  // aggregated result, [b][d][l]

// ---------------------------------------------------------------------------
// Kernel 1: projection x @ Wq + bq for Q, K, V, written transposed [b][d][l].
// grid (NL/16, NB), 256 threads. Wq staged through smem in 32-row chunks to
// avoid per-m LDG (LSU issue floor would dominate otherwise).
// ---------------------------------------------------------------------------
__global__ __launch_bounds__(256) void proj_kernel(
    const float* __restrict__ Q, const float* __restrict__ K,
    const float* __restrict__ V, const float* __restrict__ Wq,
    const float* __restrict__ bq)
{
    __shared__ float tile[16][512];   // 32 KB: 16 rows of the input
    __shared__ float wq_s[32][64];    // 8 KB: Wq chunk
    __shared__ float outT[64][17];    // padded transpose staging

    const int b   = blockIdx.y;
    const int l0  = blockIdx.x * 16;
    const int tid = threadIdx.x;

    const int dA  = (tid & 31) * 2;   // thread owns d = dA, dA+1 (float2 on Wq)
    const int g   = tid >> 5;         // 0..7
    const int ll0 = g * 2;            // thread owns rows ll0, ll0+1

    for (int mat = 0; mat < 3; ++mat) {
        const float* src = (mat == 0 ? Q : (mat == 1 ? K : V))
                         + ((size_t)b * NL + l0) * ND;
        float* dst = (mat == 0 ? g_qp : (mat == 1 ? g_kp : g_vp))
                   + (size_t)b * NDH * NL + l0;

        // load 16x512 input tile (float4, coalesced)
        #pragma unroll
        for (int i = 0; i < 8; ++i) {
            int f4  = tid + i * 256;          // 2048 float4
            int row = f4 >> 7;                // 128 float4 per row
            int col = (f4 & 127) << 2;
            *reinterpret_cast<float4*>(&tile[row][col]) =
                *reinterpret_cast<const float4*>(src + (size_t)row * ND + col);
        }
        __syncthreads();

        float a00 = 0.f, a01 = 0.f, a10 = 0.f, a11 = 0.f;
        for (int mc = 0; mc < 512; mc += 32) {
            // stage Wq[mc:mc+32][0:64] into smem
            #pragma unroll
            for (int i = 0; i < 2; ++i) {
                int f4 = tid + i * 256;       // 512 float4
                int r  = f4 >> 4;             // 16 float4 per row
                int c  = (f4 & 15) << 2;
                *reinterpret_cast<float4*>(&wq_s[r][c]) =
                    *reinterpret_cast<const float4*>(Wq + (size_t)(mc + r) * NDH + c);
            }
            __syncthreads();
            #pragma unroll
            for (int m = 0; m < 32; ++m) {
                float2 w = *reinterpret_cast<const float2*>(&wq_s[m][dA]);
                float  t0 = tile[ll0][mc + m];      // warp-broadcast LDS
                float  t1 = tile[ll0 + 1][mc + m];
                a00 += t0 * w.x; a01 += t0 * w.y;
                a10 += t1 * w.x; a11 += t1 * w.y;
            }
            __syncthreads();
        }
        float bA = bq[dA], bB = bq[dA + 1];
        outT[dA    ][ll0    ] = a00 + bA;
        outT[dA + 1][ll0    ] = a01 + bB;
        outT[dA    ][ll0 + 1] = a10 + bA;
        outT[dA + 1][ll0 + 1] = a11 + bB;
        __syncthreads();
        // coalesced transposed store: out[b][d][l0+ll]
        #pragma unroll
        for (int i = 0; i < 4; ++i) {
            int flat = tid + i * 256;   // 1024 outputs
            int d    = flat >> 4;
            int ll   = flat & 15;
            dst[(size_t)d * NL + ll] = outT[d][ll];
        }
        __syncthreads();
    }
}

// ---------------------------------------------------------------------------
// Kernel 2: per-(b,d) series. Direct circular cross-correlation
//   r[tau] = sum_n q[n] * k[(n - tau) & 1023]
// (exactly equal to real(ifft(fft(q)*conj(fft(k))))), then top-13 (ties ->
// lowest index, matching lax.top_k), softmax, and the weighted circular
// gather of v. grid (NDH, NB), 256 threads; each thread owns 4 consecutive
// taus and slides a 4-register window over k (1 new LDS per n).
// k buffer is padded (i + i>>5) so the stride-4 window load is conflict-free.
// ---------------------------------------------------------------------------
__global__ __launch_bounds__(256) void corr_kernel()
{
    __shared__ float sq[NL];
    __shared__ float skp[NL + 32];    // padded k
    __shared__ float sv[NL];
    __shared__ float sc[NL];
    __shared__ float s_tv[KTOP];
    __shared__ int   s_ti[KTOP];
    __shared__ float s_w[KTOP];
    __shared__ float red_v[8];
    __shared__ int   red_i[8];

    const int b   = blockIdx.y;
    const int d   = blockIdx.x;
    const int tid = threadIdx.x;
    const size_t rowoff = ((size_t)b * NDH + d) * NL;
    const float* qrow = g_qp + rowoff;
    const float* krow = g_kp + rowoff;
    const float* vrow = g_vp + rowoff;

    #pragma unroll
    for (int j = 0; j < 4; ++j) {
        int i = tid + j * 256;
        sq[i] = qrow[i];
        skp[i + (i >> 5)] = krow[i];
        sv[i] = vrow[i];
    }
    __syncthreads();

    const int t4 = tid * 4;
    float acc0 = 0.f, acc1 = 0.f, acc2 = 0.f, acc3 = 0.f;
    int a;
    a = (0 - t4    ) & 1023; float kr0 = skp[a + (a >> 5)];
    a = (0 - t4 - 1) & 1023; float kr1 = skp[a + (a >> 5)];
    a = (0 - t4 - 2) & 1023; float kr2 = skp[a + (a >> 5)];
    a = (0 - t4 - 3) & 1023; float kr3 = skp[a + (a >> 5)];
    a = (0 - t4) & 1023;     // tracks (n - t4) & 1023
    #pragma unroll 8
    for (int n = 0; n < NL; ++n) {
        float qn = sq[n];                 // warp-broadcast
        acc0 += qn * kr0;
        acc1 += qn * kr1;
        acc2 += qn * kr2;
        acc3 += qn * kr3;
        kr3 = kr2; kr2 = kr1; kr1 = kr0;  // register rotation (free via unroll)
        a = (a + 1) & 1023;
        kr0 = skp[a + (a >> 5)];          // 1 new k value per n
    }
    sc[t4] = acc0; sc[t4 + 1] = acc1; sc[t4 + 2] = acc2; sc[t4 + 3] = acc3;
    __syncthreads();

    // top-13 by iterated block argmax (value desc, index asc on ties)
    for (int k = 0; k < KTOP; ++k) {
        float bv = -3.0e38f; int bi = 1 << 30;
        #pragma unroll
        for (int i2 = 0; i2 < 4; ++i2) {
            int   idx = t4 + i2;
            float v   = sc[idx];
            if (v > bv || (v == bv && idx < bi)) { bv = v; bi = idx; }
        }
        #pragma unroll
        for (int off = 16; off > 0; off >>= 1) {
            float ov = __shfl_down_sync(0xffffffffu, bv, off);
            int   oi = __shfl_down_sync(0xffffffffu, bi, off);
            if (ov > bv || (ov == bv && oi < bi)) { bv = ov; bi = oi; }
        }
        if ((tid & 31) == 0) { red_v[tid >> 5] = bv; red_i[tid >> 5] = bi; }
        __syncthreads();
        if (tid == 0) {
            bv = red_v[0]; bi = red_i[0];
            #pragma unroll
            for (int w = 1; w < 8; ++w)
                if (red_v[w] > bv || (red_v[w] == bv && red_i[w] < bi)) {
                    bv = red_v[w]; bi = red_i[w];
                }
            s_tv[k] = bv; s_ti[k] = bi;
            sc[bi]  = -3.4e38f;            // exclude from next pass
        }
        __syncthreads();
    }

    // softmax over the 13 selected correlation values
    if (tid == 0) {
        float mx = s_tv[0];                // first pick is the max
        float e[KTOP], sum = 0.f;
        #pragma unroll
        for (int k = 0; k < KTOP; ++k) { e[k] = expf(s_tv[k] - mx); sum += e[k]; }
        float inv = 1.0f / sum;
        #pragma unroll
        for (int k = 0; k < KTOP; ++k) s_w[k] = e[k] * inv;
    }
    __syncthreads();

    // agg[l] = sum_k w_k * v[(l + idx_k) & 1023]
    float* aggrow = g_agg + rowoff;
    #pragma unroll
    for (int j = 0; j < 4; ++j) {
        int l = tid + j * 256;
        float acc = 0.f;
        #pragma unroll
        for (int k = 0; k < KTOP; ++k)
            acc += s_w[k] * sv[(l + s_ti[k]) & 1023];
        aggrow[l] = acc;
    }
}

// ---------------------------------------------------------------------------
// Kernel 3: transpose-broadcast agg[b][d][l] -> out[b][l][h*64+d] for h=0..7
// via padded smem tile; both gmem sides fully coalesced.
// grid (NL/32, NB), 256 threads.
// ---------------------------------------------------------------------------
__global__ __launch_bounds__(256) void out_kernel(float* __restrict__ out)
{
    __shared__ float t[64][33];
    const int b   = blockIdx.y;
    const int l0  = blockIdx.x * 32;
    const int tid = threadIdx.x;
    const float* agg = g_agg + (size_t)b * NDH * NL;

    #pragma unroll
    for (int i = 0; i < 8; ++i) {
        int flat = tid + i * 256;   // 2048 = 64 d x 32 l
        int dd   = flat >> 5;
        int ll   = flat & 31;
        t[dd][ll] = agg[(size_t)dd * NL + l0 + ll];
    }
    __syncthreads();

    float* obase = out + ((size_t)b * NL + l0) * (NDH * 8);
    #pragma unroll
    for (int i = 0; i < 64; ++i) {
        int flat = tid + i * 256;   // 16384 = 32 l x 512 ch
        int ll   = flat >> 9;
        int ch   = flat & 511;
        obase[(size_t)ll * 512 + ch] = t[ch & 63][ll];
    }
}

// ---------------------------------------------------------------------------
extern "C" void kernel_launch(void* const* d_in, const int* in_sizes, int n_in,
                              void* d_out, int out_size)
{
    const float* Q  = (const float*)d_in[0];
    const float* K  = (const float*)d_in[1];
    const float* V  = (const float*)d_in[2];
    const float* Wq = (const float*)d_in[3];
    const float* bq = (const float*)d_in[4];
    float* out = (float*)d_out;

    proj_kernel<<<dim3(NL / 16, NB), 256>>>(Q, K, V, Wq, bq);
    corr_kernel<<<dim3(NDH, NB), 256>>>();
    out_kernel<<<dim3(NL / 32, NB), 256>>>(out);
}

// round 2
// speedup vs baseline: 1.5343x; 1.5343x over previous
#include <cuda_runtime.h>
#include <math.h>

#define NB   16
#define NL   1024
#define ND   512
#define NDH  64
#define KTOP 13

typedef unsigned long long ull;

// Scratch (no allocations allowed): 4 x 4MB fp32
__device__ float g_qp[NB * NDH * NL];   // q projection, [b][d][l]
__device__ float g_kp[NB * NDH * NL];   // k projection, [b][d][l]
__device__ float g_vp[NB * NDH * NL];   // v projection, [b][d][l]
__device__ float g_agg[NB * NDH * NL];  // aggregated result, [b][d][l]

// ---- f32x2 helpers (FFMA2: only reachable via PTX fma.rn.f32x2) -----------
__device__ __forceinline__ ull pack2(float lo, float hi) {
    ull r; asm("mov.b64 %0, {%1, %2};" : "=l"(r) : "f"(lo), "f"(hi)); return r;
}
__device__ __forceinline__ void unpack2(ull v, float& lo, float& hi) {
    asm("mov.b64 {%0, %1}, %2;" : "=f"(lo), "=f"(hi) : "l"(v));
}
__device__ __forceinline__ void ffma2(ull& acc, ull a, ull b) {
    asm("fma.rn.f32x2 %0, %1, %2, %0;" : "+l"(acc) : "l"(a), "l"(b));
}

// ---------------------------------------------------------------------------
// Kernel 1: projection x @ Wq + bq, written transposed [b][d][l].
// Register-blocked SGEMM: block tile 64(l) x 64(d), BK=16, thread tile 4x4.
// A staged transposed [k][l] so inner loop = 2 x LDS.128 + 8 x FFMA2.
// grid (NL/64, NB, 3 matrices), 256 threads.
// ---------------------------------------------------------------------------
__global__ __launch_bounds__(256) void proj_kernel(
    const float* __restrict__ Q, const float* __restrict__ K,
    const float* __restrict__ V, const float* __restrict__ Wq,
    const float* __restrict__ bq)
{
    __shared__ float As[16][68];      // [k][l], stride 68 keeps 16B alignment
    __shared__ float Bs[16][64];      // [k][d]
    __shared__ float st[64][65];      // output staging for coalesced store

    const int b   = blockIdx.y;
    const int l0  = blockIdx.x * 64;
    const int mat = blockIdx.z;
    const int tid = threadIdx.x;
    const int tx  = tid & 15;         // d-group (4 d each)
    const int ty  = tid >> 4;         // l-group (4 l each)

    const float* src = (mat == 0 ? Q : (mat == 1 ? K : V))
                     + ((size_t)b * NL + l0) * ND;
    float* dst = (mat == 0 ? g_qp : (mat == 1 ? g_kp : g_vp))
               + (size_t)b * NDH * NL + l0;

    // A-tile load mapping: one float4 along k per thread
    const int arow = tid >> 2;            // 0..63 (l within tile)
    const int acq  = (tid & 3) * 4;       // k quad
    // B-tile load mapping
    const int bk   = tid >> 4;            // 0..15 (k)
    const int bc   = (tid & 15) * 4;      // d quad

    ull acc[4][2];
    #pragma unroll
    for (int i = 0; i < 4; ++i) { acc[i][0] = 0ull; acc[i][1] = 0ull; }

    for (int mc = 0; mc < ND; mc += 16) {
        float4 av = *reinterpret_cast<const float4*>(src + (size_t)arow * ND + mc + acq);
        As[acq + 0][arow] = av.x;
        As[acq + 1][arow] = av.y;
        As[acq + 2][arow] = av.z;
        As[acq + 3][arow] = av.w;
        *reinterpret_cast<float4*>(&Bs[bk][bc]) =
            *reinterpret_cast<const float4*>(Wq + (size_t)(mc + bk) * NDH + bc);
        __syncthreads();

        #pragma unroll
        for (int k = 0; k < 16; ++k) {
            float4 a4 = *reinterpret_cast<const float4*>(&As[k][ty * 4]);
            double2 bd = *reinterpret_cast<const double2*>(&Bs[k][tx * 4]);
            ull b0 = __double_as_longlong(bd.x);   // packed (d0,d1) — free reinterp
            ull b1 = __double_as_longlong(bd.y);   // packed (d2,d3)
            ull ap0 = pack2(a4.x, a4.x);
            ull ap1 = pack2(a4.y, a4.y);
            ull ap2 = pack2(a4.z, a4.z);
            ull ap3 = pack2(a4.w, a4.w);
            ffma2(acc[0][0], ap0, b0); ffma2(acc[0][1], ap0, b1);
            ffma2(acc[1][0], ap1, b0); ffma2(acc[1][1], ap1, b1);
            ffma2(acc[2][0], ap2, b0); ffma2(acc[2][1], ap2, b1);
            ffma2(acc[3][0], ap3, b0); ffma2(acc[3][1], ap3, b1);
        }
        __syncthreads();
    }

    // bias + stage transposed, then coalesced store as dst[d][l]
    float bq0 = bq[tx * 4 + 0], bq1 = bq[tx * 4 + 1];
    float bq2 = bq[tx * 4 + 2], bq3 = bq[tx * 4 + 3];
    #pragma unroll
    for (int i = 0; i < 4; ++i) {
        float v0, v1, v2, v3;
        unpack2(acc[i][0], v0, v1);
        unpack2(acc[i][1], v2, v3);
        int l = ty * 4 + i;
        st[tx * 4 + 0][l] = v0 + bq0;
        st[tx * 4 + 1][l] = v1 + bq1;
        st[tx * 4 + 2][l] = v2 + bq2;
        st[tx * 4 + 3][l] = v3 + bq3;
    }
    __syncthreads();
    #pragma unroll
    for (int i = 0; i < 16; ++i) {
        int flat = tid + i * 256;   // 4096 outputs
        int dd   = flat >> 6;
        int ll   = flat & 63;
        dst[(size_t)dd * NL + ll] = st[dd][ll];
    }
}

// ---------------------------------------------------------------------------
// Kernel 2: per-(b,d) series. r[tau] = sum_n q[n]*k[(n-tau) & 1023]
// == real(ifft(fft(q)*conj(fft(k)))). Then top-13 (ties -> lowest index),
// softmax, weighted circular gather of v.
// 128 threads, 8 taus/thread. k duplicated to length 2048 (kills the mod),
// padded +2 per 32 (conflict-free stride-8 LDS.64, keeps 8B alignment).
// Even/odd-n partials packed in f32x2 accumulators: per 2 time steps the
// loop is 2 LDS.64 + 1 unpack + 1 pack + 8 FFMA2 for 16 MACs.
// ---------------------------------------------------------------------------
#define KKPAD(i) ((i) + 2 * ((i) >> 5))

__global__ __launch_bounds__(128) void corr_kernel()
{
    __shared__ float sq[NL];
    __shared__ float skp[2176];       // 2048 dup + pad
    __shared__ float sv[NL];
    __shared__ float sc[NL];
    __shared__ float s_tv[KTOP];
    __shared__ int   s_ti[KTOP];
    __shared__ float s_w[KTOP];
    __shared__ float red_v[4];
    __shared__ int   red_i[4];

    const int b   = blockIdx.y;
    const int d   = blockIdx.x;
    const int tid = threadIdx.x;
    const size_t rowoff = ((size_t)b * NDH + d) * NL;
    const float* qrow = g_qp + rowoff;
    const float* krow = g_kp + rowoff;
    const float* vrow = g_vp + rowoff;

    #pragma unroll
    for (int j = 0; j < 8; ++j) {
        int i = tid + j * 128;
        sq[i] = qrow[i];
        sv[i] = vrow[i];
    }
    #pragma unroll
    for (int j = 0; j < 16; ++j) {
        int i = tid + j * 128;        // 0..2047
        skp[KKPAD(i)] = krow[i & 1023];
    }
    __syncthreads();

    const int t8 = tid * 8;           // first tau of this thread (even)
    const int m0 = 1024 - t8;         // base index into dup'd k (even, >= 8)

    ull acc0 = 0, acc1 = 0, acc2 = 0, acc3 = 0;
    ull acc4 = 0, acc5 = 0, acc6 = 0, acc7 = 0;

    // window: even-aligned pairs E_i = (kk[m-2i], kk[m-2i+1]),
    //         odd pairs         O_i = (kk[m-2i-1], kk[m-2i])
    ull E1 = *reinterpret_cast<const ull*>(&skp[KKPAD(m0 - 2)]);
    ull E2 = *reinterpret_cast<const ull*>(&skp[KKPAD(m0 - 4)]);
    ull E3 = *reinterpret_cast<const ull*>(&skp[KKPAD(m0 - 6)]);
    ull E4 = *reinterpret_cast<const ull*>(&skp[KKPAD(m0 - 8)]);
    float e1l, e1h, e2l, e2h, e3l, e3h, e4l, e4h;
    unpack2(E1, e1l, e1h); unpack2(E2, e2l, e2h);
    unpack2(E3, e3l, e3h); unpack2(E4, e4l, e4h);
    ull O1 = pack2(e2h, e1l);
    ull O2 = pack2(e3h, e2l);
    ull O3 = pack2(e4h, e3l);
    float prev_hi = e1h;              // kk[m-1] for the upcoming O0

    #pragma unroll 8
    for (int n = 0; n < NL; n += 2) {
        int m = m0 + n;
        ull E0 = *reinterpret_cast<const ull*>(&skp[KKPAD(m)]);
        float lo0, hi0; unpack2(E0, lo0, hi0);
        ull O0 = pack2(prev_hi, lo0);
        ull q2 = *reinterpret_cast<const ull*>(&sq[n]);   // (q[n], q[n+1])
        ffma2(acc0, q2, E0);
        ffma2(acc1, q2, O0);
        ffma2(acc2, q2, E1);
        ffma2(acc3, q2, O1);
        ffma2(acc4, q2, E2);
        ffma2(acc5, q2, O2);
        ffma2(acc6, q2, E3);
        ffma2(acc7, q2, O3);
        E3 = E2; E2 = E1; E1 = E0;
        O3 = O2; O2 = O1; O1 = O0;
        prev_hi = hi0;
    }

    // r[tau] = even-partial + odd-partial
    {
        float lo, hi;
        unpack2(acc0, lo, hi); sc[t8 + 0] = lo + hi;
        unpack2(acc1, lo, hi); sc[t8 + 1] = lo + hi;
        unpack2(acc2, lo, hi); sc[t8 + 2] = lo + hi;
        unpack2(acc3, lo, hi); sc[t8 + 3] = lo + hi;
        unpack2(acc4, lo, hi); sc[t8 + 4] = lo + hi;
        unpack2(acc5, lo, hi); sc[t8 + 5] = lo + hi;
        unpack2(acc6, lo, hi); sc[t8 + 6] = lo + hi;
        unpack2(acc7, lo, hi); sc[t8 + 7] = lo + hi;
    }
    __syncthreads();

    // top-13 by iterated block argmax (value desc, index asc on ties)
    for (int k = 0; k < KTOP; ++k) {
        float bv = -3.0e38f; int bi = 1 << 30;
        #pragma unroll
        for (int j = 0; j < 8; ++j) {
            int   idx = t8 + j;       // ascending -> strict > keeps lowest idx
            float v   = sc[idx];
            if (v > bv) { bv = v; bi = idx; }
        }
        #pragma unroll
        for (int off = 16; off > 0; off >>= 1) {
            float ov = __shfl_down_sync(0xffffffffu, bv, off);
            int   oi = __shfl_down_sync(0xffffffffu, bi, off);
            if (ov > bv || (ov == bv && oi < bi)) { bv = ov; bi = oi; }
        }
        if ((tid & 31) == 0) { red_v[tid >> 5] = bv; red_i[tid >> 5] = bi; }
        __syncthreads();
        if (tid == 0) {
            bv = red_v[0]; bi = red_i[0];
            #pragma unroll
            for (int w = 1; w < 4; ++w)
                if (red_v[w] > bv || (red_v[w] == bv && red_i[w] < bi)) {
                    bv = red_v[w]; bi = red_i[w];
                }
            s_tv[k] = bv; s_ti[k] = bi;
            sc[bi]  = -3.4e38f;       // exclude from next pass
        }
        __syncthreads();
    }

    // softmax over the 13 selected correlation values
    if (tid == 0) {
        float mx = s_tv[0];           // first pick is the max
        float e[KTOP], sum = 0.f;
        #pragma unroll
        for (int k = 0; k < KTOP; ++k) { e[k] = expf(s_tv[k] - mx); sum += e[k]; }
        float inv = 1.0f / sum;
        #pragma unroll
        for (int k = 0; k < KTOP; ++k) s_w[k] = e[k] * inv;
    }
    __syncthreads();

    // agg[l] = sum_k w_k * v[(l + idx_k) & 1023]
    float* aggrow = g_agg + rowoff;
    #pragma unroll
    for (int j = 0; j < 8; ++j) {
        int l = tid + j * 128;
        float acc = 0.f;
        #pragma unroll
        for (int k = 0; k < KTOP; ++k)
            acc += s_w[k] * sv[(l + s_ti[k]) & 1023];
        aggrow[l] = acc;
    }
}

// ---------------------------------------------------------------------------
// Kernel 3: transpose-broadcast agg[b][d][l] -> out[b][l][h*64+d], h=0..7
// ---------------------------------------------------------------------------
__global__ __launch_bounds__(256) void out_kernel(float* __restrict__ out)
{
    __shared__ float t[64][33];
    const int b   = blockIdx.y;
    const int l0  = blockIdx.x * 32;
    const int tid = threadIdx.x;
    const float* agg = g_agg + (size_t)b * NDH * NL;

    #pragma unroll
    for (int i = 0; i < 8; ++i) {
        int flat = tid + i * 256;   // 2048 = 64 d x 32 l
        int dd   = flat >> 5;
        int ll   = flat & 31;
        t[dd][ll] = agg[(size_t)dd * NL + l0 + ll];
    }
    __syncthreads();

    float* obase = out + ((size_t)b * NL + l0) * (NDH * 8);
    #pragma unroll
    for (int i = 0; i < 64; ++i) {
        int flat = tid + i * 256;   // 16384 = 32 l x 512 ch
        int ll   = flat >> 9;
        int ch   = flat & 511;
        obase[(size_t)ll * 512 + ch] = t[ch & 63][ll];
    }
}

// ---------------------------------------------------------------------------
extern "C" void kernel_launch(void* const* d_in, const int* in_sizes, int n_in,
                              void* d_out, int out_size)
{
    const float* Q  = (const float*)d_in[0];
    const float* K  = (const float*)d_in[1];
    const float* V  = (const float*)d_in[2];
    const float* Wq = (const float*)d_in[3];
    const float* bq = (const float*)d_in[4];
    float* out = (float*)d_out;

    proj_kernel<<<dim3(NL / 64, NB, 3), 256>>>(Q, K, V, Wq, bq);
    corr_kernel<<<dim3(NDH, NB), 128>>>();
    out_kernel<<<dim3(NL / 32, NB), 256>>>(out);
}

// round 3
// speedup vs baseline: 1.7255x; 1.1246x over previous
#include <cuda_runtime.h>
#include <math.h>

#define NB   16
#define NL   1024
#define ND   512
#define NDH  64
#define KTOP 13

typedef unsigned long long ull;

// Scratch (no allocations allowed): 4 x 4MB fp32
__device__ float g_qp[NB * NDH * NL];   // q projection, [b][d][l]
__device__ float g_kp[NB * NDH * NL];   // k projection, [b][d][l]
__device__ float g_vp[NB * NDH * NL];   // v projection, [b][d][l]
__device__ float g_agg[NB * NDH * NL];  // aggregated result, [b][d][l]

// ---- f32x2 helpers (FFMA2: only reachable via PTX fma.rn.f32x2) -----------
__device__ __forceinline__ ull pack2(float lo, float hi) {
    ull r; asm("mov.b64 %0, {%1, %2};" : "=l"(r) : "f"(lo), "f"(hi)); return r;
}
__device__ __forceinline__ void unpack2(ull v, float& lo, float& hi) {
    asm("mov.b64 {%0, %1}, %2;" : "=f"(lo), "=f"(hi) : "l"(v));
}
__device__ __forceinline__ void ffma2(ull& acc, ull a, ull b) {
    asm("fma.rn.f32x2 %0, %1, %2, %0;" : "+l"(acc) : "l"(a), "l"(b));
}
__device__ __forceinline__ void fadd2(ull& acc, ull a) {
    asm("add.rn.f32x2 %0, %0, %1;" : "+l"(acc) : "l"(a));
}

// ---------------------------------------------------------------------------
// Kernel 1: projection x @ Wq + bq, written transposed [b][d][l].
// Tile 128(l) x 64(d), BK=32, thread tile 8(l)x4(d) as 16 f32x2 accumulators.
// Register double-buffering: LDG for chunk c+1 issued before computing c.
// grid (NL/128, NB, 3), 256 threads.
// ---------------------------------------------------------------------------
__global__ __launch_bounds__(256) void proj_kernel(
    const float* __restrict__ Q, const float* __restrict__ K,
    const float* __restrict__ V, const float* __restrict__ Wq,
    const float* __restrict__ bq)
{
    __shared__ __align__(16) float As[32][132];   // [k][l], pad 4 (conflict-free STS)
    __shared__ __align__(16) float Bs[32][64];    // [k][d]

    const int b   = blockIdx.y;
    const int l0  = blockIdx.x * 128;
    const int mat = blockIdx.z;
    const int tid = threadIdx.x;
    const int tx  = tid & 15;          // d-quad (4 d)
    const int ty  = tid >> 4;          // l-octet (8 l)

    const float* src = (mat == 0 ? Q : (mat == 1 ? K : V))
                     + ((size_t)b * NL + l0) * ND;
    float* dst = (mat == 0 ? g_qp : (mat == 1 ? g_kp : g_vp))
               + (size_t)b * NDH * NL + l0;

    // A-load mapping: 128 rows x 32 k per chunk = 1024 float4, 4 per thread
    // B-load mapping: 32 k x 64 d = 512 float4, 2 per thread
    float4 aR[4], bR[2];
    const int ar[4] = { (tid) >> 3, (tid + 256) >> 3, (tid + 512) >> 3, (tid + 768) >> 3 };
    const int akq   = (tid & 7) * 4;
    const int bkr[2] = { tid >> 4, (tid + 256) >> 4 };
    const int bcol   = (tid & 15) * 4;

    ull acc[4][4];                      // [l-pair][d]
    #pragma unroll
    for (int i = 0; i < 4; ++i)
        #pragma unroll
        for (int j = 0; j < 4; ++j) acc[i][j] = 0ull;

    // prologue: load chunk 0
    #pragma unroll
    for (int i = 0; i < 4; ++i)
        aR[i] = *reinterpret_cast<const float4*>(src + (size_t)ar[i] * ND + akq);
    #pragma unroll
    for (int i = 0; i < 2; ++i)
        bR[i] = *reinterpret_cast<const float4*>(Wq + (size_t)bkr[i] * NDH + bcol);

    for (int c = 0; c < 16; ++c) {
        // STS chunk c (transposed A)
        #pragma unroll
        for (int i = 0; i < 4; ++i) {
            As[akq + 0][ar[i]] = aR[i].x;
            As[akq + 1][ar[i]] = aR[i].y;
            As[akq + 2][ar[i]] = aR[i].z;
            As[akq + 3][ar[i]] = aR[i].w;
        }
        #pragma unroll
        for (int i = 0; i < 2; ++i)
            *reinterpret_cast<float4*>(&Bs[bkr[i]][bcol]) = bR[i];
        __syncthreads();

        // prefetch chunk c+1 into regs (latency overlapped with compute)
        if (c < 15) {
            const int mc = (c + 1) * 32;
            #pragma unroll
            for (int i = 0; i < 4; ++i)
                aR[i] = *reinterpret_cast<const float4*>(src + (size_t)ar[i] * ND + mc + akq);
            #pragma unroll
            for (int i = 0; i < 2; ++i)
                bR[i] = *reinterpret_cast<const float4*>(Wq + (size_t)(mc + bkr[i]) * NDH + bcol);
        }

        // compute chunk c
        #pragma unroll
        for (int k = 0; k < 32; ++k) {
            double2 ad0 = *reinterpret_cast<const double2*>(&As[k][ty * 8]);
            double2 ad1 = *reinterpret_cast<const double2*>(&As[k][ty * 8 + 4]);
            float4  b4  = *reinterpret_cast<const float4*>(&Bs[k][tx * 4]);
            ull a0 = __double_as_longlong(ad0.x);
            ull a1 = __double_as_longlong(ad0.y);
            ull a2 = __double_as_longlong(ad1.x);
            ull a3 = __double_as_longlong(ad1.y);
            ull b0 = pack2(b4.x, b4.x);
            ull b1 = pack2(b4.y, b4.y);
            ull b2 = pack2(b4.z, b4.z);
            ull b3 = pack2(b4.w, b4.w);
            ffma2(acc[0][0], a0, b0); ffma2(acc[0][1], a0, b1);
            ffma2(acc[0][2], a0, b2); ffma2(acc[0][3], a0, b3);
            ffma2(acc[1][0], a1, b0); ffma2(acc[1][1], a1, b1);
            ffma2(acc[1][2], a1, b2); ffma2(acc[1][3], a1, b3);
            ffma2(acc[2][0], a2, b0); ffma2(acc[2][1], a2, b1);
            ffma2(acc[2][2], a2, b2); ffma2(acc[2][3], a2, b3);
            ffma2(acc[3][0], a3, b0); ffma2(acc[3][1], a3, b1);
            ffma2(acc[3][2], a3, b2); ffma2(acc[3][3], a3, b3);
        }
        __syncthreads();
    }

    // epilogue: bias + direct transposed store (thread owns 4 d-rows x 8 l)
    float4 bias = *reinterpret_cast<const float4*>(&bq[tx * 4]);
    ull bb[4] = { pack2(bias.x, bias.x), pack2(bias.y, bias.y),
                  pack2(bias.z, bias.z), pack2(bias.w, bias.w) };
    #pragma unroll
    for (int di = 0; di < 4; ++di) {
        #pragma unroll
        for (int lp = 0; lp < 4; ++lp) fadd2(acc[lp][di], bb[di]);
        float4 r0, r1;
        unpack2(acc[0][di], r0.x, r0.y); unpack2(acc[1][di], r0.z, r0.w);
        unpack2(acc[2][di], r1.x, r1.y); unpack2(acc[3][di], r1.z, r1.w);
        float* p = dst + (size_t)(tx * 4 + di) * NL + ty * 8;
        *reinterpret_cast<float4*>(p)     = r0;
        *reinterpret_cast<float4*>(p + 4) = r1;
    }
}

// ---------------------------------------------------------------------------
// Kernel 2: per-(b,d) series. r[tau] = sum_n q[n]*k[(n-tau) & 1023]
// == real(ifft(fft(q)*conj(fft(k)))). Then top-13 (ties -> lowest index),
// softmax, weighted circular gather of v.
// 64 threads, 16 taus/thread. k duplicated to length 2048, padded 2-per-16.
// Since tau0 = 16*tid, the padded base address advances by a CONSTANT (+18)
// per 16-n outer step -> zero per-iteration address math. Even/odd-n partials
// packed in f32x2: per 2 n the loop is 2 LDS + 1 pack + 16 FFMA2 (32 MACs).
// ---------------------------------------------------------------------------
#define KP16(i) ((i) + 2 * ((i) >> 4))

__global__ __launch_bounds__(64) void corr_kernel()
{
    __shared__ __align__(16) float sq[NL];
    __shared__ __align__(16) float skp[2304];   // 2048 dup + 2-per-16 pad
    __shared__ __align__(16) float sv[NL];
    __shared__ float sc[NL];
    __shared__ float s_tv[KTOP];
    __shared__ int   s_ti[KTOP];
    __shared__ float s_w[KTOP];
    __shared__ float red_v[2];
    __shared__ int   red_i[2];

    const int b   = blockIdx.y;
    const int d   = blockIdx.x;
    const int tid = threadIdx.x;
    const size_t rowoff = ((size_t)b * NDH + d) * NL;
    const float* qrow = g_qp + rowoff;
    const float* krow = g_kp + rowoff;
    const float* vrow = g_vp + rowoff;

    #pragma unroll
    for (int j = 0; j < 16; ++j) {
        int i = tid + j * 64;
        sq[i] = qrow[i];
        sv[i] = vrow[i];
    }
    #pragma unroll
    for (int j = 0; j < 32; ++j) {
        int i = tid + j * 64;          // 0..2047
        skp[KP16(i)] = krow[i & 1023];
    }
    __syncthreads();

    const int t16 = tid * 16;
    const int m0  = 1024 - t16;        // m0 % 16 == 0, m0 >= 16
    const int pb0 = KP16(m0);

    // window: E[j] = pair(m0 + n - 2j); O[j] = (k[..-2j-1], k[..-2j])
    ull E1 = *reinterpret_cast<const ull*>(&skp[pb0 -  4]);
    ull E2 = *reinterpret_cast<const ull*>(&skp[pb0 -  6]);
    ull E3 = *reinterpret_cast<const ull*>(&skp[pb0 -  8]);
    ull E4 = *reinterpret_cast<const ull*>(&skp[pb0 - 10]);
    ull E5 = *reinterpret_cast<const ull*>(&skp[pb0 - 12]);
    ull E6 = *reinterpret_cast<const ull*>(&skp[pb0 - 14]);
    ull E7 = *reinterpret_cast<const ull*>(&skp[pb0 - 16]);
    ull E8 = *reinterpret_cast<const ull*>(&skp[pb0 - 18]);
    float tl, th, tl2, th2;
    unpack2(E1, tl, th);
    float prev_hi = th;
    ull O1, O2, O3, O4, O5, O6, O7;
    unpack2(E2, tl2, th2); O1 = pack2(th2, tl);
    unpack2(E3, tl,  th ); O2 = pack2(th,  tl2);
    unpack2(E4, tl2, th2); O3 = pack2(th2, tl);
    unpack2(E5, tl,  th ); O4 = pack2(th,  tl2);
    unpack2(E6, tl2, th2); O5 = pack2(th2, tl);
    unpack2(E7, tl,  th ); O6 = pack2(th,  tl2);
    unpack2(E8, tl2, th2); O7 = pack2(th2, tl);

    ull ae0=0,ae1=0,ae2=0,ae3=0,ae4=0,ae5=0,ae6=0,ae7=0;
    ull ao0=0,ao1=0,ao2=0,ao3=0,ao4=0,ao5=0,ao6=0,ao7=0;

    int pb = pb0;                       // padded address of pair(m0 + n0)
    for (int n0 = 0; n0 < NL; n0 += 16) {
        #pragma unroll
        for (int j = 0; j < 8; ++j) {
            ull E0 = *reinterpret_cast<const ull*>(&skp[pb + 2 * j]);
            float lo0, hi0; unpack2(E0, lo0, hi0);
            ull O0 = pack2(prev_hi, lo0);
            ull q2 = *reinterpret_cast<const ull*>(&sq[n0 + 2 * j]);
            ffma2(ae0, q2, E0); ffma2(ao0, q2, O0);
            ffma2(ae1, q2, E1); ffma2(ao1, q2, O1);
            ffma2(ae2, q2, E2); ffma2(ao2, q2, O2);
            ffma2(ae3, q2, E3); ffma2(ao3, q2, O3);
            ffma2(ae4, q2, E4); ffma2(ao4, q2, O4);
            ffma2(ae5, q2, E5); ffma2(ao5, q2, O5);
            ffma2(ae6, q2, E6); ffma2(ao6, q2, O6);
            ffma2(ae7, q2, E7); ffma2(ao7, q2, O7);
            E7 = E6; E6 = E5; E5 = E4; E4 = E3; E3 = E2; E2 = E1; E1 = E0;
            O7 = O6; O6 = O5; O5 = O4; O4 = O3; O3 = O2; O2 = O1; O1 = O0;
            prev_hi = hi0;
        }
        pb += 18;                       // 16 elements + 2 pad, linear!
    }

    {
        float lo, hi;
        unpack2(ae0, lo, hi); sc[t16 +  0] = lo + hi;
        unpack2(ao0, lo, hi); sc[t16 +  1] = lo + hi;
        unpack2(ae1, lo, hi); sc[t16 +  2] = lo + hi;
        unpack2(ao1, lo, hi); sc[t16 +  3] = lo + hi;
        unpack2(ae2, lo, hi); sc[t16 +  4] = lo + hi;
        unpack2(ao2, lo, hi); sc[t16 +  5] = lo + hi;
        unpack2(ae3, lo, hi); sc[t16 +  6] = lo + hi;
        unpack2(ao3, lo, hi); sc[t16 +  7] = lo + hi;
        unpack2(ae4, lo, hi); sc[t16 +  8] = lo + hi;
        unpack2(ao4, lo, hi); sc[t16 +  9] = lo + hi;
        unpack2(ae5, lo, hi); sc[t16 + 10] = lo + hi;
        unpack2(ao5, lo, hi); sc[t16 + 11] = lo + hi;
        unpack2(ae6, lo, hi); sc[t16 + 12] = lo + hi;
        unpack2(ao6, lo, hi); sc[t16 + 13] = lo + hi;
        unpack2(ae7, lo, hi); sc[t16 + 14] = lo + hi;
        unpack2(ao7, lo, hi); sc[t16 + 15] = lo + hi;
    }
    __syncthreads();

    // top-13 by iterated argmax (value desc, index asc on ties)
    for (int k = 0; k < KTOP; ++k) {
        float bv = -3.0e38f; int bi = 1 << 30;
        #pragma unroll
        for (int j = 0; j < 16; ++j) {
            int   idx = t16 + j;       // ascending -> strict > keeps lowest idx
            float v   = sc[idx];
            if (v > bv) { bv = v; bi = idx; }
        }
        #pragma unroll
        for (int off = 16; off > 0; off >>= 1) {
            float ov = __shfl_down_sync(0xffffffffu, bv, off);
            int   oi = __shfl_down_sync(0xffffffffu, bi, off);
            if (ov > bv || (ov == bv && oi < bi)) { bv = ov; bi = oi; }
        }
        if ((tid & 31) == 0) { red_v[tid >> 5] = bv; red_i[tid >> 5] = bi; }
        __syncthreads();
        if (tid == 0) {
            bv = red_v[0]; bi = red_i[0];
            if (red_v[1] > bv || (red_v[1] == bv && red_i[1] < bi)) {
                bv = red_v[1]; bi = red_i[1];
            }
            s_tv[k] = bv; s_ti[k] = bi;
            sc[bi]  = -3.4e38f;        // exclude from next pass
        }
        __syncthreads();
    }

    // softmax over the 13 selected correlation values
    if (tid == 0) {
        float mx = s_tv[0];            // first pick is the max
        float e[KTOP], sum = 0.f;
        #pragma unroll
        for (int k = 0; k < KTOP; ++k) { e[k] = expf(s_tv[k] - mx); sum += e[k]; }
        float inv = 1.0f / sum;
        #pragma unroll
        for (int k = 0; k < KTOP; ++k) s_w[k] = e[k] * inv;
    }
    __syncthreads();

    // agg[l] = sum_k w_k * v[(l + idx_k) & 1023]
    float* aggrow = g_agg + rowoff;
    #pragma unroll
    for (int j = 0; j < 16; ++j) {
        int l = tid + j * 64;
        float acc = 0.f;
        #pragma unroll
        for (int k = 0; k < KTOP; ++k)
            acc += s_w[k] * sv[(l + s_ti[k]) & 1023];
        aggrow[l] = acc;
    }
}

// ---------------------------------------------------------------------------
// Kernel 3: transpose-broadcast agg[b][d][l] -> out[b][l][h*64+d], h=0..7
// ---------------------------------------------------------------------------
__global__ __launch_bounds__(256) void out_kernel(float* __restrict__ out)
{
    __shared__ float t[64][33];
    const int b   = blockIdx.y;
    const int l0  = blockIdx.x * 32;
    const int tid = threadIdx.x;
    const float* agg = g_agg + (size_t)b * NDH * NL;

    #pragma unroll
    for (int i = 0; i < 8; ++i) {
        int flat = tid + i * 256;   // 2048 = 64 d x 32 l
        int dd   = flat >> 5;
        int ll   = flat & 31;
        t[dd][ll] = agg[(size_t)dd * NL + l0 + ll];
    }
    __syncthreads();

    float* obase = out + ((size_t)b * NL + l0) * (NDH * 8);
    #pragma unroll
    for (int i = 0; i < 16; ++i) {
        int f4  = tid + i * 256;    // 4096 float4 = 32 l x 128 ch4
        int ll  = f4 >> 7;
        int c0  = (f4 & 127) * 4;
        int cc  = c0 & 63;
        float4 v = make_float4(t[cc][ll], t[cc + 1][ll], t[cc + 2][ll], t[cc + 3][ll]);
        *reinterpret_cast<float4*>(obase + (size_t)ll * 512 + c0) = v;
    }
}

// ---------------------------------------------------------------------------
extern "C" void kernel_launch(void* const* d_in, const int* in_sizes, int n_in,
                              void* d_out, int out_size)
{
    const float* Q  = (const float*)d_in[0];
    const float* K  = (const float*)d_in[1];
    const float* V  = (const float*)d_in[2];
    const float* Wq = (const float*)d_in[3];
    const float* bq = (const float*)d_in[4];
    float* out = (float*)d_out;

    proj_kernel<<<dim3(NL / 128, NB, 3), 256>>>(Q, K, V, Wq, bq);
    corr_kernel<<<dim3(NDH, NB), 64>>>();
    out_kernel<<<dim3(NL / 32, NB), 256>>>(out);
}